// round 8
// baseline (speedup 1.0000x reference)
#include <cuda_runtime.h>
#include <cstdint>

// Problem constants
#define Bb   8
#define Np   8192
#define Sp   2048
#define Kp   32
#define Dp   128
#define C0   131          // D + 3
#define C1P  132          // padded layer-1 input channels
#define M0   128
#define M1   128
#define M2   256
#define HIDp 8
#define LEAKYF 0.1f
#define FLATN (M2*HIDp)   // 2048

// MLP tiling
#define QB   2            // queries per CTA
#define RR   (QB*Kp)      // 64 rows (m)
#define RP   68           // padded m-stride (floats)

// Scratch (device globals: allocation-free rule)
__device__ float g_flat[(size_t)Bb * Sp * FLATN];   // 134 MB
__device__ float g_ptsT[(size_t)Bb * Np * Dp];      // 32 MB  [b][n][c]
__device__ int   g_knn[Bb * Sp * Kp];               // 2 MB
__device__ float g_w1T[C1P * M0];                   // c-major w1 [132][128]
__device__ float g_w2T[M0 * M1];                    // c-major w2 [128][128]
__device__ float g_w3T[M1 * M2];                    // c-major w3 [128][256]

__device__ __forceinline__ float lrelu(float x) { return x > 0.0f ? x : LEAKYF * x; }

// ---- packed fp32x2 helpers (Blackwell sm_100+; bit-exact vs 2x fmaf) ----
typedef unsigned long long u64t;
__device__ __forceinline__ void ffma2(u64t& d, u64t a, u64t b) {
    asm("fma.rn.f32x2 %0, %1, %2, %0;" : "+l"(d) : "l"(a), "l"(b));
}
__device__ __forceinline__ u64t dup2(float x) {
    u64t r; asm("mov.b64 %0, {%1, %2};" : "=l"(r) : "f"(x), "f"(x)); return r;
}
__device__ __forceinline__ float2 unpack2(u64t v) {
    float2 r; asm("mov.b64 {%0, %1}, %2;" : "=f"(r.x), "=f"(r.y) : "l"(v)); return r;
}

// ---------------------------------------------------------------------------
// Prep kernels: transpose weights to c-major
// ---------------------------------------------------------------------------
__global__ void prep_w1T_kernel(const float* __restrict__ w1)
{
    int idx = blockIdx.x * blockDim.x + threadIdx.x;   // c*128 + o
    if (idx >= C1P * M0) return;
    int c = idx >> 7, o = idx & 127;
    g_w1T[idx] = (c < C0) ? w1[o * C0 + c] : 0.0f;
}
__global__ void prep_w2T_kernel(const float* __restrict__ w2)
{
    int idx = blockIdx.x * blockDim.x + threadIdx.x;
    if (idx >= M0 * M1) return;
    int c = idx >> 7, o = idx & 127;
    g_w2T[idx] = w2[o * M0 + c];
}
__global__ void prep_w3T_kernel(const float* __restrict__ w3)
{
    int idx = blockIdx.x * blockDim.x + threadIdx.x;   // c*256 + o
    if (idx >= M1 * M2) return;
    int c = idx >> 8, o = idx & 255;
    g_w3T[idx] = w3[o * M1 + c];
}

// ---------------------------------------------------------------------------
// Kernel 0: copy new_xyz = xyz[:, :, :S] to output head
// ---------------------------------------------------------------------------
__global__ void copy_newxyz_kernel(const float* __restrict__ xyz, float* __restrict__ out)
{
    int idx = blockIdx.x * blockDim.x + threadIdx.x;
    if (idx >= Bb * 3 * Sp) return;
    int b = idx / (3 * Sp);
    int r = idx - b * 3 * Sp;
    int c = r / Sp;
    int s = r - c * Sp;
    out[idx] = xyz[(b * 3 + c) * Np + s];
}

// ---------------------------------------------------------------------------
// Kernel 1: transpose points [B][D][N] -> ptsT [B][N][D]
// ---------------------------------------------------------------------------
__global__ void transpose_kernel(const float* __restrict__ p)
{
    __shared__ float tile[32][33];
    int b  = blockIdx.z;
    int nb = blockIdx.x * 32;
    int cb = blockIdx.y * 32;
    int tx = threadIdx.x;
    int ty = threadIdx.y;
    const float* src = p + (size_t)b * Dp * Np;
    float* dst = g_ptsT + (size_t)b * Np * Dp;
    #pragma unroll
    for (int j = ty; j < 32; j += 8)
        tile[j][tx] = src[(size_t)(cb + j) * Np + nb + tx];
    __syncthreads();
    #pragma unroll
    for (int j = ty; j < 32; j += 8)
        dst[(size_t)(nb + j) * Dp + cb + tx] = tile[tx][j];
}

// ---------------------------------------------------------------------------
// Kernel 2: KNN, hierarchical. 8 warps x 1024 points. Each warp emits its
// sorted top-32 via shuffle-only argmin rounds (no block barriers); warp 0
// merges the 8 sorted lists. Comparator everywhere: (d, idx) lexicographic
// min — identical selection to jax top_k(-sqr) with index tie-break.
// ---------------------------------------------------------------------------
__global__ void __launch_bounds__(256) knn_kernel(const float* __restrict__ xyz)
{
    const int bs = blockIdx.x;
    const int b  = bs >> 11;
    const int s  = bs & (Sp - 1);
    const float* X = xyz + (size_t)b * 3 * Np;
    const int t    = threadIdx.x;
    const int warp = t >> 5;
    const int lane = t & 31;
    const int base = warp << 10;            // 1024 points per warp

    const float qx = X[s], qy = X[Np + s], qz = X[2 * Np + s];
    const float qq = qx * qx + qy * qy + qz * qz;

    float d[32];
    #pragma unroll
    for (int i = 0; i < 32; i++) {
        int n = base + lane + (i << 5);
        float px = X[n], py = X[Np + n], pz = X[2 * Np + n];
        float pp  = px * px + py * py + pz * pz;
        float dot = qx * px + qy * py + qz * pz;
        d[i] = (qq + pp) - 2.0f * dot;
    }

    // per-lane running min; ascending-i scan with strict < keeps the smallest
    // i on ties, and for fixed lane idx = base + lane + (i<<5) grows with i,
    // so per-lane winner is the smallest idx. Cross-lane ties: comparator.
    float lbv = d[0]; int lbs = 0;
    #pragma unroll
    for (int i = 1; i < 32; i++) if (d[i] < lbv) { lbv = d[i]; lbs = i; }

    __shared__ float sd[8][32];
    __shared__ int   si[8][32];

    #pragma unroll 1
    for (int r = 0; r < Kp; r++) {
        float v  = lbv;
        int   id = base + lane + (lbs << 5);
        #pragma unroll
        for (int off = 16; off > 0; off >>= 1) {
            float v2 = __shfl_down_sync(0xffffffffu, v, off);
            int   i2 = __shfl_down_sync(0xffffffffu, id, off);
            if (v2 < v || (v2 == v && i2 < id)) { v = v2; id = i2; }
        }
        v  = __shfl_sync(0xffffffffu, v, 0);
        id = __shfl_sync(0xffffffffu, id, 0);
        if (lane == 0) { sd[warp][r] = v; si[warp][r] = id; }
        if (lane == (id & 31)) {
            int slot = (id - base) >> 5;
            #pragma unroll
            for (int i = 0; i < 32; i++) if (i == slot) d[i] = 3.0e38f;
            lbv = d[0]; lbs = 0;
            #pragma unroll
            for (int i = 1; i < 32; i++) if (d[i] < lbv) { lbv = d[i]; lbs = i; }
        }
        __syncwarp();
    }
    __syncthreads();

    // merge 8 sorted lists (warp 0): per round, 8-way argmin over list heads
    if (warp == 0) {
        int head = 0;
        #pragma unroll 1
        for (int r = 0; r < Kp; r++) {
            float v  = (lane < 8) ? sd[lane][head] : 3.0e38f;
            int   id = (lane < 8) ? si[lane][head] : 0x7fffffff;
            int   src = lane;
            #pragma unroll
            for (int off = 4; off > 0; off >>= 1) {
                float v2 = __shfl_down_sync(0xffffffffu, v, off);
                int   i2 = __shfl_down_sync(0xffffffffu, id, off);
                int   s2 = __shfl_down_sync(0xffffffffu, src, off);
                if (v2 < v || (v2 == v && i2 < id)) { v = v2; id = i2; src = s2; }
            }
            int idw  = __shfl_sync(0xffffffffu, id, 0);
            int srcw = __shfl_sync(0xffffffffu, src, 0);
            if (lane == 0) g_knn[bs * Kp + r] = idw;
            if (lane == srcw) head++;
            __syncwarp();
        }
    }
}

// ---------------------------------------------------------------------------
// Kernel 3: MLP stack as SGEMM. One CTA = 2 queries (64 rows), 128 threads.
// Inner loops use packed fp32x2 FMA (2 FMAs/instr, bit-exact).
// ---------------------------------------------------------------------------
#define SMEM_BUF_F (C1P * RP)         // 8976 floats: feats -> h2
#define SMEM_BUF_H (M0 * RP)          // 8704 floats: h1 -> h3-half
#define SMEM_SWB   (16 * 128)         // 2048 floats
#define SMEM_SWM   (QB * Kp * HIDp)   // 512 floats
#define SMEM_FLOATS (SMEM_BUF_F + SMEM_BUF_H + SMEM_SWB + SMEM_SWM)
#define SMEM_BYTES  (SMEM_FLOATS * 4 + RR * 4)

template<int C, int BK>
__device__ __forceinline__ void gemm_layer(
    const float* __restrict__ Asrc,   // smem [C][RP]
    const float* __restrict__ Wsrc,   // global c-major [C][wstride]
    int wstride, int woff,
    float* __restrict__ swB,          // smem [BK][128]
    float* __restrict__ dest,         // smem [128][RP]
    int t, int o0, int o1, int m0, int m1)
{
    constexpr int NV = (BK * 128) / 512;   // float4 stages per thread
    u64t accp[8][4];                  // [o][m-pair]
    #pragma unroll
    for (int j = 0; j < 8; j++)
        #pragma unroll
        for (int i = 0; i < 4; i++) accp[j][i] = 0ull;

    // prefetch chunk 0 into registers
    float4 wreg[NV];
    #pragma unroll
    for (int v = 0; v < NV; v++) {
        int idx = 4 * t + 512 * v;
        int r = idx >> 7, o = idx & 127;
        wreg[v] = *(const float4*)&Wsrc[(size_t)r * wstride + woff + o];
    }

    #pragma unroll 1
    for (int c0 = 0; c0 < C; c0 += BK) {
        __syncthreads();                       // prev compute done with swB
        #pragma unroll
        for (int v = 0; v < NV; v++)
            *(float4*)&swB[4 * t + 512 * v] = wreg[v];
        if (c0 + BK < C) {                     // prefetch next chunk
            #pragma unroll
            for (int v = 0; v < NV; v++) {
                int idx = 4 * t + 512 * v;
                int r = idx >> 7, o = idx & 127;
                wreg[v] = *(const float4*)&Wsrc[(size_t)(c0 + BK + r) * wstride + woff + o];
            }
        }
        __syncthreads();
        #pragma unroll
        for (int kk = 0; kk < BK; kk++) {
            const float* arow = Asrc + (c0 + kk) * RP;
            // m-pairs loaded directly as packed f32x2 (16B-aligned)
            ulonglong2 av0 = *(const ulonglong2*)&arow[m0];
            ulonglong2 av1 = *(const ulonglong2*)&arow[m1];
            u64t am2[4] = {av0.x, av0.y, av1.x, av1.y};
            float4 b0 = *(const float4*)&swB[kk * 128 + o0];
            float4 b1 = *(const float4*)&swB[kk * 128 + o1];
            float bo[8] = {b0.x, b0.y, b0.z, b0.w, b1.x, b1.y, b1.z, b1.w};
            #pragma unroll
            for (int j = 0; j < 8; j++) {
                u64t bd = dup2(bo[j]);
                #pragma unroll
                for (int i = 0; i < 4; i++)
                    ffma2(accp[j][i], bd, am2[i]);
            }
        }
    }
    __syncthreads();
    #pragma unroll
    for (int j = 0; j < 8; j++) {
        int o = (j < 4) ? (o0 + j) : (o1 + j - 4);
        float2 p0 = unpack2(accp[j][0]);
        float2 p1 = unpack2(accp[j][1]);
        float2 p2 = unpack2(accp[j][2]);
        float2 p3 = unpack2(accp[j][3]);
        float4 v0, v1;
        v0.x = lrelu(p0.x); v0.y = lrelu(p0.y);
        v0.z = lrelu(p1.x); v0.w = lrelu(p1.y);
        v1.x = lrelu(p2.x); v1.y = lrelu(p2.y);
        v1.z = lrelu(p3.x); v1.w = lrelu(p3.y);
        *(float4*)&dest[o * RP + m0] = v0;
        *(float4*)&dest[o * RP + m1] = v1;
    }
}

__global__ void __launch_bounds__(128) mlp_kernel(const float* __restrict__ xyz,
    const float* __restrict__ wn1, const float* __restrict__ wb1,
    const float* __restrict__ wn2, const float* __restrict__ wb2,
    const float* __restrict__ wn3, const float* __restrict__ wb3)
{
    extern __shared__ float sm[];
    float* bufF = sm;                          // [132][RP]  feats -> h2
    float* bufH = bufF + SMEM_BUF_F;           // [128][RP]  h1 -> h3-half
    float* swB  = bufH + SMEM_BUF_H;           // [16][128]
    float* swm  = swB + SMEM_SWB;              // [64][8]
    int*   sidx = (int*)(swm + SMEM_SWM);      // [64]

    const int pair = blockIdx.x;               // 0..8191
    const int b    = pair >> 10;
    const int t    = threadIdx.x;
    const int tx = t & 15, ty = t >> 4;
    const int o0 = tx * 4, o1 = tx * 4 + 64;
    const int m0 = ty * 4, m1 = ty * 4 + 32;

    const float* X  = xyz + (size_t)b * 3 * Np;
    const float* PT = g_ptsT + (size_t)b * Np * Dp;

    if (t < RR) sidx[t] = g_knn[(size_t)(pair * 2 + (t >> 5)) * Kp + (t & 31)];
    __syncthreads();

    #pragma unroll 4
    for (int m = 0; m < RR; m++) {
        int n = sidx[m];
        bufF[(3 + t) * RP + m] = PT[(size_t)n * Dp + t];
    }
    for (int idx = t; idx < RR * 3; idx += 128) {
        int m = idx / 3, c = idx - m * 3;
        int n = sidx[m];
        int sq = ((pair * 2 + (m >> 5)) & (Sp - 1));
        bufF[c * RP + m] = X[c * Np + n] - X[c * Np + sq];
    }
    if (t < RR) bufF[C0 * RP + t] = 0.0f;
    __syncthreads();

    if (t < RR) {
        float dx = bufF[0 * RP + t], dy = bufF[1 * RP + t], dz = bufF[2 * RP + t];
        float h[8], g[8];
        #pragma unroll
        for (int o = 0; o < 8; o++) {
            float a = wn1[o * 3 + 0] * dx + wn1[o * 3 + 1] * dy + wn1[o * 3 + 2] * dz + wb1[o];
            h[o] = a > 0.0f ? a : 0.0f;
        }
        #pragma unroll
        for (int o = 0; o < 8; o++) {
            float a = wb2[o];
            #pragma unroll
            for (int c = 0; c < 8; c++) a += wn2[o * 8 + c] * h[c];
            g[o] = a > 0.0f ? a : 0.0f;
        }
        #pragma unroll
        for (int o = 0; o < 8; o++) {
            float a = wb3[o];
            #pragma unroll
            for (int c = 0; c < 8; c++) a += wn3[o * 8 + c] * g[c];
            swm[t * 8 + o] = a > 0.0f ? a : 0.0f;
        }
    }

    gemm_layer<C1P, 12>(bufF, g_w1T, 128, 0, swB, bufH, t, o0, o1, m0, m1);
    __syncthreads();
    gemm_layer<M0, 16>(bufH, g_w2T, 128, 0, swB, bufF, t, o0, o1, m0, m1);
    __syncthreads();

    #pragma unroll 1
    for (int p = 0; p < 2; p++) {
        gemm_layer<M1, 16>(bufF, g_w3T, 256, 128 * p, swB, bufH, t, o0, o1, m0, m1);
        __syncthreads();
        {
            int q  = t >> 6;
            int ob = t & 63;
            int gq = pair * 2 + q;
            float* fo = g_flat + (size_t)gq * FLATN + (size_t)(128 * p) * 8;
            const float* wmq = swm + q * Kp * 8;
            #pragma unroll
            for (int oo = 0; oo < 2; oo++) {
                int o = ob + 64 * oo;
                const float* hrow = bufH + o * RP + q * Kp;
                u64t ag2[4];
                #pragma unroll
                for (int w = 0; w < 4; w++) ag2[w] = 0ull;
                #pragma unroll 4
                for (int k = 0; k < Kp; k++) {
                    float h = hrow[k];
                    u64t hd = dup2(h);
                    ulonglong2 wv0 = *(const ulonglong2*)&wmq[k * 8];      // 32B aligned
                    ulonglong2 wv1 = *(const ulonglong2*)&wmq[k * 8 + 4];
                    ffma2(ag2[0], hd, wv0.x);
                    ffma2(ag2[1], hd, wv0.y);
                    ffma2(ag2[2], hd, wv1.x);
                    ffma2(ag2[3], hd, wv1.y);
                }
                float2 g0 = unpack2(ag2[0]), g1 = unpack2(ag2[1]);
                float2 g2 = unpack2(ag2[2]), g3 = unpack2(ag2[3]);
                *(float4*)&fo[o * 8]     = make_float4(g0.x, g0.y, g1.x, g1.y);
                *(float4*)&fo[o * 8 + 4] = make_float4(g2.x, g2.y, g3.x, g3.y);
            }
        }
        __syncthreads();
    }
}

// ---------------------------------------------------------------------------
// Kernel 4: out = lrelu(flat[16384,2048] @ wlin[256,2048]^T) -> out[b][o][s]
// 64x64x16 tile, register prefetch, packed fp32x2 inner product.
// ---------------------------------------------------------------------------
#define BM 64
#define BN 64
#define BKk 16

__global__ void __launch_bounds__(256) out_gemm_kernel(
    const float* __restrict__ Wl, float* __restrict__ outp)
{
    __shared__ float As[BKk][BM];
    __shared__ float Bs[BKk][BN];

    const int bm = blockIdx.x;
    const int bn = blockIdx.y;
    const int t  = threadIdx.x;
    const int mm0 = bm * BM, nn0 = bn * BN;
    const int tx = t & 15, ty = t >> 4;
    const int lr = t >> 2;
    const int lc = (t & 3) * 4;

    const float* A = g_flat;

    u64t accp[4][2];    // [m][n-pair]
    #pragma unroll
    for (int i = 0; i < 4; i++) { accp[i][0] = 0ull; accp[i][1] = 0ull; }

    // prefetch chunk 0
    float4 a  = *(const float4*)(A  + (size_t)(mm0 + lr) * FLATN + lc);
    float4 bq = *(const float4*)(Wl + (size_t)(nn0 + lr) * FLATN + lc);

    #pragma unroll 1
    for (int k0 = 0; k0 < FLATN; k0 += BKk) {
        __syncthreads();                       // prev compute done with As/Bs
        As[lc + 0][lr] = a.x; As[lc + 1][lr] = a.y; As[lc + 2][lr] = a.z; As[lc + 3][lr] = a.w;
        Bs[lc + 0][lr] = bq.x; Bs[lc + 1][lr] = bq.y; Bs[lc + 2][lr] = bq.z; Bs[lc + 3][lr] = bq.w;
        if (k0 + BKk < FLATN) {                // prefetch next chunk
            a  = *(const float4*)(A  + (size_t)(mm0 + lr) * FLATN + k0 + BKk + lc);
            bq = *(const float4*)(Wl + (size_t)(nn0 + lr) * FLATN + k0 + BKk + lc);
        }
        __syncthreads();
        #pragma unroll
        for (int k = 0; k < BKk; k++) {
            float4 av = *(const float4*)&As[k][ty * 4];
            ulonglong2 bv = *(const ulonglong2*)&Bs[k][tx * 4];   // n-pairs, 16B aligned
            float aa[4] = {av.x, av.y, av.z, av.w};
            #pragma unroll
            for (int i = 0; i < 4; i++) {
                u64t ad = dup2(aa[i]);
                ffma2(accp[i][0], ad, bv.x);
                ffma2(accp[i][1], ad, bv.y);
            }
        }
    }

    #pragma unroll
    for (int i = 0; i < 4; i++) {
        int mm = mm0 + ty * 4 + i;
        int bb = mm >> 11, ss = mm & (Sp - 1);
        float* ob = outp + (size_t)bb * M2 * Sp + ss;
        float2 p0 = unpack2(accp[i][0]);
        float2 p1 = unpack2(accp[i][1]);
        float r[4] = {p0.x, p0.y, p1.x, p1.y};
        #pragma unroll
        for (int j = 0; j < 4; j++) {
            ob[(size_t)(nn0 + tx * 4 + j) * Sp] = lrelu(r[j]);
        }
    }
}

// ---------------------------------------------------------------------------
// Launcher
// ---------------------------------------------------------------------------
extern "C" void kernel_launch(void* const* d_in, const int* in_sizes, int n_in,
                              void* d_out, int out_size)
{
    const float* xyz  = (const float*)d_in[0];
    const float* pts  = (const float*)d_in[1];
    const float* w1   = (const float*)d_in[2];
    const float* w2   = (const float*)d_in[3];
    const float* w3   = (const float*)d_in[4];
    const float* wn1  = (const float*)d_in[5];
    const float* wb1  = (const float*)d_in[6];
    const float* wn2  = (const float*)d_in[7];
    const float* wb2  = (const float*)d_in[8];
    const float* wn3  = (const float*)d_in[9];
    const float* wb3  = (const float*)d_in[10];
    const float* wlin = (const float*)d_in[11];
    float* out = (float*)d_out;

    prep_w1T_kernel<<<(C1P * M0 + 255) / 256, 256>>>(w1);
    prep_w2T_kernel<<<(M0 * M1 + 255) / 256, 256>>>(w2);
    prep_w3T_kernel<<<(M1 * M2 + 255) / 256, 256>>>(w3);

    copy_newxyz_kernel<<<(Bb * 3 * Sp + 255) / 256, 256>>>(xyz, out);

    {
        dim3 g(Np / 32, Dp / 32, Bb);
        dim3 blk(32, 8);
        transpose_kernel<<<g, blk>>>(pts);
    }

    knn_kernel<<<Bb * Sp, 256>>>(xyz);

    cudaFuncSetAttribute(mlp_kernel, cudaFuncAttributeMaxDynamicSharedMemorySize, SMEM_BYTES);
    mlp_kernel<<<Bb * Sp / QB, 128, SMEM_BYTES>>>(xyz,
                                                  wn1, wb1, wn2, wb2, wn3, wb3);

    {
        dim3 g((Bb * Sp) / BM, M2 / BN);
        out_gemm_kernel<<<g, 256>>>(wlin, out + Bb * 3 * Sp);
    }
}

// round 9
// speedup vs baseline: 1.2588x; 1.2588x over previous
#include <cuda_runtime.h>
#include <cstdint>

// Problem constants
#define Bb   8
#define Np   8192
#define Sp   2048
#define Kp   32
#define Dp   128
#define C0   131          // D + 3
#define C1P  132          // padded layer-1 input channels
#define M0   128
#define M1   128
#define M2   256
#define HIDp 8
#define LEAKYF 0.1f
#define FLATN (M2*HIDp)   // 2048

// MLP tiling
#define QB   2            // queries per CTA
#define RR   (QB*Kp)      // 64 rows (m)
#define RP   68           // padded m-stride (floats)

// Scratch (device globals: allocation-free rule)
__device__ float g_flat[(size_t)Bb * Sp * FLATN];   // 134 MB
__device__ float g_ptsT[(size_t)Bb * Np * Dp];      // 32 MB  [b][n][c]
__device__ int   g_knn[Bb * Sp * Kp];               // 2 MB
__device__ float g_w1T[C1P * M0];                   // c-major w1 [132][128]
__device__ float g_w2T[M0 * M1];                    // c-major w2 [128][128]
__device__ float g_w3T[M1 * M2];                    // c-major w3 [128][256]

__device__ __forceinline__ float lrelu(float x) { return x > 0.0f ? x : LEAKYF * x; }

// ---- packed fp32x2 helpers (Blackwell sm_100+; bit-exact vs 2x fmaf) ----
typedef unsigned long long u64t;
__device__ __forceinline__ void ffma2(u64t& d, u64t a, u64t b) {
    asm("fma.rn.f32x2 %0, %1, %2, %0;" : "+l"(d) : "l"(a), "l"(b));
}
__device__ __forceinline__ u64t dup2(float x) {
    u64t r; asm("mov.b64 %0, {%1, %2};" : "=l"(r) : "f"(x), "f"(x)); return r;
}
__device__ __forceinline__ float2 unpack2(u64t v) {
    float2 r; asm("mov.b64 {%0, %1}, %2;" : "=f"(r.x), "=f"(r.y) : "l"(v)); return r;
}

// ---------------------------------------------------------------------------
// Prep kernels: transpose weights to c-major
// ---------------------------------------------------------------------------
__global__ void prep_w1T_kernel(const float* __restrict__ w1)
{
    int idx = blockIdx.x * blockDim.x + threadIdx.x;   // c*128 + o
    if (idx >= C1P * M0) return;
    int c = idx >> 7, o = idx & 127;
    g_w1T[idx] = (c < C0) ? w1[o * C0 + c] : 0.0f;
}
__global__ void prep_w2T_kernel(const float* __restrict__ w2)
{
    int idx = blockIdx.x * blockDim.x + threadIdx.x;
    if (idx >= M0 * M1) return;
    int c = idx >> 7, o = idx & 127;
    g_w2T[idx] = w2[o * M0 + c];
}
__global__ void prep_w3T_kernel(const float* __restrict__ w3)
{
    int idx = blockIdx.x * blockDim.x + threadIdx.x;   // c*256 + o
    if (idx >= M1 * M2) return;
    int c = idx >> 8, o = idx & 255;
    g_w3T[idx] = w3[o * M1 + c];
}

// ---------------------------------------------------------------------------
// Kernel 0: copy new_xyz = xyz[:, :, :S] to output head
// ---------------------------------------------------------------------------
__global__ void copy_newxyz_kernel(const float* __restrict__ xyz, float* __restrict__ out)
{
    int idx = blockIdx.x * blockDim.x + threadIdx.x;
    if (idx >= Bb * 3 * Sp) return;
    int b = idx / (3 * Sp);
    int r = idx - b * 3 * Sp;
    int c = r / Sp;
    int s = r - c * Sp;
    out[idx] = xyz[(b * 3 + c) * Np + s];
}

// ---------------------------------------------------------------------------
// Kernel 1: transpose points [B][D][N] -> ptsT [B][N][D]
// ---------------------------------------------------------------------------
__global__ void transpose_kernel(const float* __restrict__ p)
{
    __shared__ float tile[32][33];
    int b  = blockIdx.z;
    int nb = blockIdx.x * 32;
    int cb = blockIdx.y * 32;
    int tx = threadIdx.x;
    int ty = threadIdx.y;
    const float* src = p + (size_t)b * Dp * Np;
    float* dst = g_ptsT + (size_t)b * Np * Dp;
    #pragma unroll
    for (int j = ty; j < 32; j += 8)
        tile[j][tx] = src[(size_t)(cb + j) * Np + nb + tx];
    __syncthreads();
    #pragma unroll
    for (int j = ty; j < 32; j += 8)
        dst[(size_t)(nb + j) * Dp + cb + tx] = tile[tx][j];
}

// ---------------------------------------------------------------------------
// Kernel 2: KNN, block version (proven), 2 queries per CTA.
// One CTA handles queries s0=2*pair, s1=2*pair+1: points loaded once,
// both selections run between the same barrier pair per round
// (warp 0 reduces q0, warp 1 reduces q1). Per-query semantics identical to
// jax top_k(-sqr) with index tie-break.
// ---------------------------------------------------------------------------
__global__ void __launch_bounds__(256) knn_kernel(const float* __restrict__ xyz)
{
    const int pair = blockIdx.x;              // 0..8191
    const int b    = pair >> 10;
    const int s0   = (pair << 1) & (Sp - 1);
    const int s1   = s0 + 1;
    const float* X = xyz + (size_t)b * 3 * Np;
    const int t = threadIdx.x;

    const float q0x = X[s0], q0y = X[Np + s0], q0z = X[2 * Np + s0];
    const float q1x = X[s1], q1y = X[Np + s1], q1z = X[2 * Np + s1];
    const float qq0 = q0x * q0x + q0y * q0y + q0z * q0z;
    const float qq1 = q1x * q1x + q1y * q1y + q1z * q1z;

    float d0[32], d1[32];
    #pragma unroll
    for (int i = 0; i < 32; i++) {
        int n = t + (i << 8);
        float px = X[n], py = X[Np + n], pz = X[2 * Np + n];
        float pp = px * px + py * py + pz * pz;
        d0[i] = (qq0 + pp) - 2.0f * (q0x * px + q0y * py + q0z * pz);
        d1[i] = (qq1 + pp) - 2.0f * (q1x * px + q1y * py + q1z * pz);
    }

    float lb0 = d0[0]; int ls0 = 0;
    float lb1 = d1[0]; int ls1 = 0;
    #pragma unroll
    for (int i = 1; i < 32; i++) {
        if (d0[i] < lb0) { lb0 = d0[i]; ls0 = i; }
        if (d1[i] < lb1) { lb1 = d1[i]; ls1 = i; }
    }

    __shared__ float bv0[256], bv1[256];
    __shared__ int   bi0[256], bi1[256];
    __shared__ int   s_cur0, s_cur1;

    for (int r = 0; r < Kp; r++) {
        bv0[t] = lb0; bi0[t] = t + (ls0 << 8);
        bv1[t] = lb1; bi1[t] = t + (ls1 << 8);
        __syncthreads();
        if (t < 32) {              // warp 0 reduces query 0
            float v = bv0[t]; int id = bi0[t];
            #pragma unroll
            for (int j = 1; j < 8; j++) {
                float v2 = bv0[t + 32 * j]; int i2 = bi0[t + 32 * j];
                if (v2 < v || (v2 == v && i2 < id)) { v = v2; id = i2; }
            }
            #pragma unroll
            for (int off = 16; off > 0; off >>= 1) {
                float v2 = __shfl_down_sync(0xffffffffu, v, off);
                int   i2 = __shfl_down_sync(0xffffffffu, id, off);
                if (v2 < v || (v2 == v && i2 < id)) { v = v2; id = i2; }
            }
            if (t == 0) {
                s_cur0 = id;
                g_knn[(size_t)(pair * 2) * Kp + r] = id;
            }
        } else if (t < 64) {       // warp 1 reduces query 1
            int l = t - 32;
            float v = bv1[l]; int id = bi1[l];
            #pragma unroll
            for (int j = 1; j < 8; j++) {
                float v2 = bv1[l + 32 * j]; int i2 = bi1[l + 32 * j];
                if (v2 < v || (v2 == v && i2 < id)) { v = v2; id = i2; }
            }
            #pragma unroll
            for (int off = 16; off > 0; off >>= 1) {
                float v2 = __shfl_down_sync(0xffffffffu, v, off);
                int   i2 = __shfl_down_sync(0xffffffffu, id, off);
                if (v2 < v || (v2 == v && i2 < id)) { v = v2; id = i2; }
            }
            if (l == 0) {
                s_cur1 = id;
                g_knn[(size_t)(pair * 2 + 1) * Kp + r] = id;
            }
        }
        __syncthreads();
        int c0 = s_cur0;
        if ((c0 & 255) == t) {
            int slot = c0 >> 8;
            #pragma unroll
            for (int i = 0; i < 32; i++) if (i == slot) d0[i] = 3.0e38f;
            lb0 = d0[0]; ls0 = 0;
            #pragma unroll
            for (int i = 1; i < 32; i++) if (d0[i] < lb0) { lb0 = d0[i]; ls0 = i; }
        }
        int c1 = s_cur1;
        if ((c1 & 255) == t) {
            int slot = c1 >> 8;
            #pragma unroll
            for (int i = 0; i < 32; i++) if (i == slot) d1[i] = 3.0e38f;
            lb1 = d1[0]; ls1 = 0;
            #pragma unroll
            for (int i = 1; i < 32; i++) if (d1[i] < lb1) { lb1 = d1[i]; ls1 = i; }
        }
    }
}

// ---------------------------------------------------------------------------
// Kernel 3: MLP stack as SGEMM. One CTA = 2 queries (64 rows), 128 threads.
// Inner loops use packed fp32x2 FMA (2 FMAs/instr, bit-exact).
// ---------------------------------------------------------------------------
#define SMEM_BUF_F (C1P * RP)         // 8976 floats: feats -> h2
#define SMEM_BUF_H (M0 * RP)          // 8704 floats: h1 -> h3-half
#define SMEM_SWB   (16 * 128)         // 2048 floats
#define SMEM_SWM   (QB * Kp * HIDp)   // 512 floats
#define SMEM_FLOATS (SMEM_BUF_F + SMEM_BUF_H + SMEM_SWB + SMEM_SWM)
#define SMEM_BYTES  (SMEM_FLOATS * 4 + RR * 4)

template<int C, int BK>
__device__ __forceinline__ void gemm_layer(
    const float* __restrict__ Asrc,   // smem [C][RP]
    const float* __restrict__ Wsrc,   // global c-major [C][wstride]
    int wstride, int woff,
    float* __restrict__ swB,          // smem [BK][128]
    float* __restrict__ dest,         // smem [128][RP]
    int t, int o0, int o1, int m0, int m1)
{
    constexpr int NV = (BK * 128) / 512;   // float4 stages per thread
    u64t accp[8][4];                  // [o][m-pair]
    #pragma unroll
    for (int j = 0; j < 8; j++)
        #pragma unroll
        for (int i = 0; i < 4; i++) accp[j][i] = 0ull;

    // prefetch chunk 0 into registers
    float4 wreg[NV];
    #pragma unroll
    for (int v = 0; v < NV; v++) {
        int idx = 4 * t + 512 * v;
        int r = idx >> 7, o = idx & 127;
        wreg[v] = *(const float4*)&Wsrc[(size_t)r * wstride + woff + o];
    }

    #pragma unroll 1
    for (int c0 = 0; c0 < C; c0 += BK) {
        __syncthreads();                       // prev compute done with swB
        #pragma unroll
        for (int v = 0; v < NV; v++)
            *(float4*)&swB[4 * t + 512 * v] = wreg[v];
        if (c0 + BK < C) {                     // prefetch next chunk
            #pragma unroll
            for (int v = 0; v < NV; v++) {
                int idx = 4 * t + 512 * v;
                int r = idx >> 7, o = idx & 127;
                wreg[v] = *(const float4*)&Wsrc[(size_t)(c0 + BK + r) * wstride + woff + o];
            }
        }
        __syncthreads();
        #pragma unroll
        for (int kk = 0; kk < BK; kk++) {
            const float* arow = Asrc + (c0 + kk) * RP;
            // m-pairs loaded directly as packed f32x2 (16B-aligned)
            ulonglong2 av0 = *(const ulonglong2*)&arow[m0];
            ulonglong2 av1 = *(const ulonglong2*)&arow[m1];
            u64t am2[4] = {av0.x, av0.y, av1.x, av1.y};
            float4 b0 = *(const float4*)&swB[kk * 128 + o0];
            float4 b1 = *(const float4*)&swB[kk * 128 + o1];
            float bo[8] = {b0.x, b0.y, b0.z, b0.w, b1.x, b1.y, b1.z, b1.w};
            #pragma unroll
            for (int j = 0; j < 8; j++) {
                u64t bd = dup2(bo[j]);
                #pragma unroll
                for (int i = 0; i < 4; i++)
                    ffma2(accp[j][i], bd, am2[i]);
            }
        }
    }
    __syncthreads();
    #pragma unroll
    for (int j = 0; j < 8; j++) {
        int o = (j < 4) ? (o0 + j) : (o1 + j - 4);
        float2 p0 = unpack2(accp[j][0]);
        float2 p1 = unpack2(accp[j][1]);
        float2 p2 = unpack2(accp[j][2]);
        float2 p3 = unpack2(accp[j][3]);
        float4 v0, v1;
        v0.x = lrelu(p0.x); v0.y = lrelu(p0.y);
        v0.z = lrelu(p1.x); v0.w = lrelu(p1.y);
        v1.x = lrelu(p2.x); v1.y = lrelu(p2.y);
        v1.z = lrelu(p3.x); v1.w = lrelu(p3.y);
        *(float4*)&dest[o * RP + m0] = v0;
        *(float4*)&dest[o * RP + m1] = v1;
    }
}

__global__ void __launch_bounds__(128) mlp_kernel(const float* __restrict__ xyz,
    const float* __restrict__ wn1, const float* __restrict__ wb1,
    const float* __restrict__ wn2, const float* __restrict__ wb2,
    const float* __restrict__ wn3, const float* __restrict__ wb3)
{
    extern __shared__ float sm[];
    float* bufF = sm;                          // [132][RP]  feats -> h2
    float* bufH = bufF + SMEM_BUF_F;           // [128][RP]  h1 -> h3-half
    float* swB  = bufH + SMEM_BUF_H;           // [16][128]
    float* swm  = swB + SMEM_SWB;              // [64][8]
    int*   sidx = (int*)(swm + SMEM_SWM);      // [64]

    const int pair = blockIdx.x;               // 0..8191
    const int b    = pair >> 10;
    const int t    = threadIdx.x;
    const int tx = t & 15, ty = t >> 4;
    const int o0 = tx * 4, o1 = tx * 4 + 64;
    const int m0 = ty * 4, m1 = ty * 4 + 32;

    const float* X  = xyz + (size_t)b * 3 * Np;
    const float* PT = g_ptsT + (size_t)b * Np * Dp;

    if (t < RR) sidx[t] = g_knn[(size_t)(pair * 2 + (t >> 5)) * Kp + (t & 31)];
    __syncthreads();

    #pragma unroll 4
    for (int m = 0; m < RR; m++) {
        int n = sidx[m];
        bufF[(3 + t) * RP + m] = PT[(size_t)n * Dp + t];
    }
    for (int idx = t; idx < RR * 3; idx += 128) {
        int m = idx / 3, c = idx - m * 3;
        int n = sidx[m];
        int sq = ((pair * 2 + (m >> 5)) & (Sp - 1));
        bufF[c * RP + m] = X[c * Np + n] - X[c * Np + sq];
    }
    if (t < RR) bufF[C0 * RP + t] = 0.0f;
    __syncthreads();

    if (t < RR) {
        float dx = bufF[0 * RP + t], dy = bufF[1 * RP + t], dz = bufF[2 * RP + t];
        float h[8], g[8];
        #pragma unroll
        for (int o = 0; o < 8; o++) {
            float a = wn1[o * 3 + 0] * dx + wn1[o * 3 + 1] * dy + wn1[o * 3 + 2] * dz + wb1[o];
            h[o] = a > 0.0f ? a : 0.0f;
        }
        #pragma unroll
        for (int o = 0; o < 8; o++) {
            float a = wb2[o];
            #pragma unroll
            for (int c = 0; c < 8; c++) a += wn2[o * 8 + c] * h[c];
            g[o] = a > 0.0f ? a : 0.0f;
        }
        #pragma unroll
        for (int o = 0; o < 8; o++) {
            float a = wb3[o];
            #pragma unroll
            for (int c = 0; c < 8; c++) a += wn3[o * 8 + c] * g[c];
            swm[t * 8 + o] = a > 0.0f ? a : 0.0f;
        }
    }

    gemm_layer<C1P, 12>(bufF, g_w1T, 128, 0, swB, bufH, t, o0, o1, m0, m1);
    __syncthreads();
    gemm_layer<M0, 16>(bufH, g_w2T, 128, 0, swB, bufF, t, o0, o1, m0, m1);
    __syncthreads();

    #pragma unroll 1
    for (int p = 0; p < 2; p++) {
        gemm_layer<M1, 16>(bufF, g_w3T, 256, 128 * p, swB, bufH, t, o0, o1, m0, m1);
        __syncthreads();
        {
            int q  = t >> 6;
            int ob = t & 63;
            int gq = pair * 2 + q;
            float* fo = g_flat + (size_t)gq * FLATN + (size_t)(128 * p) * 8;
            const float* wmq = swm + q * Kp * 8;
            #pragma unroll
            for (int oo = 0; oo < 2; oo++) {
                int o = ob + 64 * oo;
                const float* hrow = bufH + o * RP + q * Kp;
                u64t ag2[4];
                #pragma unroll
                for (int w = 0; w < 4; w++) ag2[w] = 0ull;
                #pragma unroll 4
                for (int k = 0; k < Kp; k++) {
                    float h = hrow[k];
                    u64t hd = dup2(h);
                    ulonglong2 wv0 = *(const ulonglong2*)&wmq[k * 8];      // 32B aligned
                    ulonglong2 wv1 = *(const ulonglong2*)&wmq[k * 8 + 4];
                    ffma2(ag2[0], hd, wv0.x);
                    ffma2(ag2[1], hd, wv0.y);
                    ffma2(ag2[2], hd, wv1.x);
                    ffma2(ag2[3], hd, wv1.y);
                }
                float2 g0 = unpack2(ag2[0]), g1 = unpack2(ag2[1]);
                float2 g2 = unpack2(ag2[2]), g3 = unpack2(ag2[3]);
                *(float4*)&fo[o * 8]     = make_float4(g0.x, g0.y, g1.x, g1.y);
                *(float4*)&fo[o * 8 + 4] = make_float4(g2.x, g2.y, g3.x, g3.y);
            }
        }
        __syncthreads();
    }
}

// ---------------------------------------------------------------------------
// Kernel 4: out = lrelu(flat[16384,2048] @ wlin[256,2048]^T) -> out[b][o][s]
// 64x64x16 tile, register prefetch, packed fp32x2 inner product.
// ---------------------------------------------------------------------------
#define BM 64
#define BN 64
#define BKk 16

__global__ void __launch_bounds__(256) out_gemm_kernel(
    const float* __restrict__ Wl, float* __restrict__ outp)
{
    __shared__ float As[BKk][BM];
    __shared__ float Bs[BKk][BN];

    const int bm = blockIdx.x;
    const int bn = blockIdx.y;
    const int t  = threadIdx.x;
    const int mm0 = bm * BM, nn0 = bn * BN;
    const int tx = t & 15, ty = t >> 4;
    const int lr = t >> 2;
    const int lc = (t & 3) * 4;

    const float* A = g_flat;

    u64t accp[4][2];    // [m][n-pair]
    #pragma unroll
    for (int i = 0; i < 4; i++) { accp[i][0] = 0ull; accp[i][1] = 0ull; }

    // prefetch chunk 0
    float4 a  = *(const float4*)(A  + (size_t)(mm0 + lr) * FLATN + lc);
    float4 bq = *(const float4*)(Wl + (size_t)(nn0 + lr) * FLATN + lc);

    #pragma unroll 1
    for (int k0 = 0; k0 < FLATN; k0 += BKk) {
        __syncthreads();                       // prev compute done with As/Bs
        As[lc + 0][lr] = a.x; As[lc + 1][lr] = a.y; As[lc + 2][lr] = a.z; As[lc + 3][lr] = a.w;
        Bs[lc + 0][lr] = bq.x; Bs[lc + 1][lr] = bq.y; Bs[lc + 2][lr] = bq.z; Bs[lc + 3][lr] = bq.w;
        if (k0 + BKk < FLATN) {                // prefetch next chunk
            a  = *(const float4*)(A  + (size_t)(mm0 + lr) * FLATN + k0 + BKk + lc);
            bq = *(const float4*)(Wl + (size_t)(nn0 + lr) * FLATN + k0 + BKk + lc);
        }
        __syncthreads();
        #pragma unroll
        for (int k = 0; k < BKk; k++) {
            float4 av = *(const float4*)&As[k][ty * 4];
            ulonglong2 bv = *(const ulonglong2*)&Bs[k][tx * 4];   // n-pairs, 16B aligned
            float aa[4] = {av.x, av.y, av.z, av.w};
            #pragma unroll
            for (int i = 0; i < 4; i++) {
                u64t ad = dup2(aa[i]);
                ffma2(accp[i][0], ad, bv.x);
                ffma2(accp[i][1], ad, bv.y);
            }
        }
    }

    #pragma unroll
    for (int i = 0; i < 4; i++) {
        int mm = mm0 + ty * 4 + i;
        int bb = mm >> 11, ss = mm & (Sp - 1);
        float* ob = outp + (size_t)bb * M2 * Sp + ss;
        float2 p0 = unpack2(accp[i][0]);
        float2 p1 = unpack2(accp[i][1]);
        float r[4] = {p0.x, p0.y, p1.x, p1.y};
        #pragma unroll
        for (int j = 0; j < 4; j++) {
            ob[(size_t)(nn0 + tx * 4 + j) * Sp] = lrelu(r[j]);
        }
    }
}

// ---------------------------------------------------------------------------
// Launcher
// ---------------------------------------------------------------------------
extern "C" void kernel_launch(void* const* d_in, const int* in_sizes, int n_in,
                              void* d_out, int out_size)
{
    const float* xyz  = (const float*)d_in[0];
    const float* pts  = (const float*)d_in[1];
    const float* w1   = (const float*)d_in[2];
    const float* w2   = (const float*)d_in[3];
    const float* w3   = (const float*)d_in[4];
    const float* wn1  = (const float*)d_in[5];
    const float* wb1  = (const float*)d_in[6];
    const float* wn2  = (const float*)d_in[7];
    const float* wb2  = (const float*)d_in[8];
    const float* wn3  = (const float*)d_in[9];
    const float* wb3  = (const float*)d_in[10];
    const float* wlin = (const float*)d_in[11];
    float* out = (float*)d_out;

    prep_w1T_kernel<<<(C1P * M0 + 255) / 256, 256>>>(w1);
    prep_w2T_kernel<<<(M0 * M1 + 255) / 256, 256>>>(w2);
    prep_w3T_kernel<<<(M1 * M2 + 255) / 256, 256>>>(w3);

    copy_newxyz_kernel<<<(Bb * 3 * Sp + 255) / 256, 256>>>(xyz, out);

    {
        dim3 g(Np / 32, Dp / 32, Bb);
        dim3 blk(32, 8);
        transpose_kernel<<<g, blk>>>(pts);
    }

    knn_kernel<<<Bb * Sp / 2, 256>>>(xyz);

    cudaFuncSetAttribute(mlp_kernel, cudaFuncAttributeMaxDynamicSharedMemorySize, SMEM_BYTES);
    mlp_kernel<<<Bb * Sp / QB, 128, SMEM_BYTES>>>(xyz,
                                                  wn1, wb1, wn2, wb2, wn3, wb3);

    {
        dim3 g((Bb * Sp) / BM, M2 / BN);
        out_gemm_kernel<<<g, 256>>>(wlin, out + Bb * 3 * Sp);
    }
}

// round 10
// speedup vs baseline: 1.3774x; 1.0942x over previous
#include <cuda_runtime.h>
#include <cstdint>

// Problem constants
#define Bb   8
#define Np   8192
#define Sp   2048
#define Kp   32
#define Dp   128
#define C0   131          // D + 3
#define C1P  132          // padded layer-1 input channels
#define M0   128
#define M1   128
#define M2   256
#define HIDp 8
#define LEAKYF 0.1f
#define FLATN (M2*HIDp)   // 2048

// MLP tiling
#define QB   2            // queries per CTA
#define RR   (QB*Kp)      // 64 rows (m)
#define RP   68           // padded m-stride (floats)

// Scratch (device globals: allocation-free rule)
__device__ float g_flat[(size_t)Bb * Sp * FLATN];   // 134 MB
__device__ float g_ptsT[(size_t)Bb * Np * Dp];      // 32 MB  [b][n][c]
__device__ int   g_knn[Bb * Sp * Kp];               // 2 MB
__device__ float g_w1T[C1P * M0];                   // c-major w1 [132][128]
__device__ float g_w2T[M0 * M1];                    // c-major w2 [128][128]
__device__ float g_w3T[M1 * M2];                    // c-major w3 [128][256]

__device__ __forceinline__ float lrelu(float x) { return x > 0.0f ? x : LEAKYF * x; }

// ---- packed fp32x2 helpers (Blackwell sm_100+; bit-exact vs 2x fmaf) ----
typedef unsigned long long u64t;
__device__ __forceinline__ void ffma2(u64t& d, u64t a, u64t b) {
    asm("fma.rn.f32x2 %0, %1, %2, %0;" : "+l"(d) : "l"(a), "l"(b));
}
__device__ __forceinline__ u64t dup2(float x) {
    u64t r; asm("mov.b64 %0, {%1, %2};" : "=l"(r) : "f"(x), "f"(x)); return r;
}
__device__ __forceinline__ float2 unpack2(u64t v) {
    float2 r; asm("mov.b64 {%0, %1}, %2;" : "=f"(r.x), "=f"(r.y) : "l"(v)); return r;
}

// ---------------------------------------------------------------------------
// Prep kernels: transpose weights to c-major
// ---------------------------------------------------------------------------
__global__ void prep_w1T_kernel(const float* __restrict__ w1)
{
    int idx = blockIdx.x * blockDim.x + threadIdx.x;   // c*128 + o
    if (idx >= C1P * M0) return;
    int c = idx >> 7, o = idx & 127;
    g_w1T[idx] = (c < C0) ? w1[o * C0 + c] : 0.0f;
}
__global__ void prep_w2T_kernel(const float* __restrict__ w2)
{
    int idx = blockIdx.x * blockDim.x + threadIdx.x;
    if (idx >= M0 * M1) return;
    int c = idx >> 7, o = idx & 127;
    g_w2T[idx] = w2[o * M0 + c];
}
__global__ void prep_w3T_kernel(const float* __restrict__ w3)
{
    int idx = blockIdx.x * blockDim.x + threadIdx.x;   // c*256 + o
    if (idx >= M1 * M2) return;
    int c = idx >> 8, o = idx & 255;
    g_w3T[idx] = w3[o * M1 + c];
}

// ---------------------------------------------------------------------------
// Kernel 0: copy new_xyz = xyz[:, :, :S] to output head
// ---------------------------------------------------------------------------
__global__ void copy_newxyz_kernel(const float* __restrict__ xyz, float* __restrict__ out)
{
    int idx = blockIdx.x * blockDim.x + threadIdx.x;
    if (idx >= Bb * 3 * Sp) return;
    int b = idx / (3 * Sp);
    int r = idx - b * 3 * Sp;
    int c = r / Sp;
    int s = r - c * Sp;
    out[idx] = xyz[(b * 3 + c) * Np + s];
}

// ---------------------------------------------------------------------------
// Kernel 1: transpose points [B][D][N] -> ptsT [B][N][D]
// ---------------------------------------------------------------------------
__global__ void transpose_kernel(const float* __restrict__ p)
{
    __shared__ float tile[32][33];
    int b  = blockIdx.z;
    int nb = blockIdx.x * 32;
    int cb = blockIdx.y * 32;
    int tx = threadIdx.x;
    int ty = threadIdx.y;
    const float* src = p + (size_t)b * Dp * Np;
    float* dst = g_ptsT + (size_t)b * Np * Dp;
    #pragma unroll
    for (int j = ty; j < 32; j += 8)
        tile[j][tx] = src[(size_t)(cb + j) * Np + nb + tx];
    __syncthreads();
    #pragma unroll
    for (int j = ty; j < 32; j += 8)
        dst[(size_t)(nb + j) * Dp + cb + tx] = tile[tx][j];
}

// ---------------------------------------------------------------------------
// Kernel 2: KNN, round-7 block version (proven fastest).
// Matches jax top_k(-sqr) with index tie-break.
// ---------------------------------------------------------------------------
__global__ void __launch_bounds__(256) knn_kernel(const float* __restrict__ xyz)
{
    const int bs = blockIdx.x;
    const int b  = bs >> 11;
    const int s  = bs & (Sp - 1);
    const float* X = xyz + (size_t)b * 3 * Np;
    const int t = threadIdx.x;

    const float qx = X[s], qy = X[Np + s], qz = X[2 * Np + s];
    const float qq = qx * qx + qy * qy + qz * qz;

    float d[32];
    #pragma unroll
    for (int i = 0; i < 32; i++) {
        int n = t + (i << 8);
        float px = X[n], py = X[Np + n], pz = X[2 * Np + n];
        float pp  = px * px + py * py + pz * pz;
        float dot = qx * px + qy * py + qz * pz;
        d[i] = (qq + pp) - 2.0f * dot;
    }

    float lbv = d[0]; int lbs = 0;
    #pragma unroll
    for (int i = 1; i < 32; i++) if (d[i] < lbv) { lbv = d[i]; lbs = i; }

    __shared__ float bv[256];
    __shared__ int   bi[256];
    __shared__ int   s_sel[Kp];
    __shared__ int   s_cur;

    for (int r = 0; r < Kp; r++) {
        bv[t] = lbv;
        bi[t] = t + (lbs << 8);
        __syncthreads();
        if (t < 32) {
            float v = bv[t]; int id = bi[t];
            #pragma unroll
            for (int j = 1; j < 8; j++) {
                float v2 = bv[t + 32 * j]; int i2 = bi[t + 32 * j];
                if (v2 < v || (v2 == v && i2 < id)) { v = v2; id = i2; }
            }
            #pragma unroll
            for (int off = 16; off > 0; off >>= 1) {
                float v2 = __shfl_down_sync(0xffffffffu, v, off);
                int   i2 = __shfl_down_sync(0xffffffffu, id, off);
                if (v2 < v || (v2 == v && i2 < id)) { v = v2; id = i2; }
            }
            if (t == 0) { s_sel[r] = id; s_cur = id; }
        }
        __syncthreads();
        int cid = s_cur;
        if ((cid & 255) == t) {
            int slot = cid >> 8;
            #pragma unroll
            for (int i = 0; i < 32; i++) if (i == slot) d[i] = 3.0e38f;
            lbv = d[0]; lbs = 0;
            #pragma unroll
            for (int i = 1; i < 32; i++) if (d[i] < lbv) { lbv = d[i]; lbs = i; }
        }
    }
    if (t < Kp) g_knn[bs * Kp + t] = s_sel[t];
}

// ---------------------------------------------------------------------------
// Kernel 3: MLP stack as SGEMM. One CTA = 2 queries (64 rows), 128 threads.
// Inner loops use packed fp32x2 FMA (2 FMAs/instr, bit-exact).
// ---------------------------------------------------------------------------
#define SMEM_BUF_F (C1P * RP)         // 8976 floats: feats -> h2
#define SMEM_BUF_H (M0 * RP)          // 8704 floats: h1 -> h3-half
#define SMEM_SWB   (16 * 128)         // 2048 floats
#define SMEM_SWM   (QB * Kp * HIDp)   // 512 floats
#define SMEM_FLOATS (SMEM_BUF_F + SMEM_BUF_H + SMEM_SWB + SMEM_SWM)
#define SMEM_BYTES  (SMEM_FLOATS * 4 + RR * 4)

template<int C, int BK>
__device__ __forceinline__ void gemm_layer(
    const float* __restrict__ Asrc,   // smem [C][RP]
    const float* __restrict__ Wsrc,   // global c-major [C][wstride]
    int wstride, int woff,
    float* __restrict__ swB,          // smem [BK][128]
    float* __restrict__ dest,         // smem [128][RP]
    int t, int o0, int o1, int m0, int m1)
{
    constexpr int NV = (BK * 128) / 512;   // float4 stages per thread
    u64t accp[8][4];                  // [o][m-pair]
    #pragma unroll
    for (int j = 0; j < 8; j++)
        #pragma unroll
        for (int i = 0; i < 4; i++) accp[j][i] = 0ull;

    // prefetch chunk 0 into registers
    float4 wreg[NV];
    #pragma unroll
    for (int v = 0; v < NV; v++) {
        int idx = 4 * t + 512 * v;
        int r = idx >> 7, o = idx & 127;
        wreg[v] = *(const float4*)&Wsrc[(size_t)r * wstride + woff + o];
    }

    #pragma unroll 1
    for (int c0 = 0; c0 < C; c0 += BK) {
        __syncthreads();                       // prev compute done with swB
        #pragma unroll
        for (int v = 0; v < NV; v++)
            *(float4*)&swB[4 * t + 512 * v] = wreg[v];
        if (c0 + BK < C) {                     // prefetch next chunk
            #pragma unroll
            for (int v = 0; v < NV; v++) {
                int idx = 4 * t + 512 * v;
                int r = idx >> 7, o = idx & 127;
                wreg[v] = *(const float4*)&Wsrc[(size_t)(c0 + BK + r) * wstride + woff + o];
            }
        }
        __syncthreads();
        #pragma unroll
        for (int kk = 0; kk < BK; kk++) {
            const float* arow = Asrc + (c0 + kk) * RP;
            // m-pairs loaded directly as packed f32x2 (16B-aligned)
            ulonglong2 av0 = *(const ulonglong2*)&arow[m0];
            ulonglong2 av1 = *(const ulonglong2*)&arow[m1];
            u64t am2[4] = {av0.x, av0.y, av1.x, av1.y};
            float4 b0 = *(const float4*)&swB[kk * 128 + o0];
            float4 b1 = *(const float4*)&swB[kk * 128 + o1];
            float bo[8] = {b0.x, b0.y, b0.z, b0.w, b1.x, b1.y, b1.z, b1.w};
            #pragma unroll
            for (int j = 0; j < 8; j++) {
                u64t bd = dup2(bo[j]);
                #pragma unroll
                for (int i = 0; i < 4; i++)
                    ffma2(accp[j][i], bd, am2[i]);
            }
        }
    }
    __syncthreads();
    #pragma unroll
    for (int j = 0; j < 8; j++) {
        int o = (j < 4) ? (o0 + j) : (o1 + j - 4);
        float2 p0 = unpack2(accp[j][0]);
        float2 p1 = unpack2(accp[j][1]);
        float2 p2 = unpack2(accp[j][2]);
        float2 p3 = unpack2(accp[j][3]);
        float4 v0, v1;
        v0.x = lrelu(p0.x); v0.y = lrelu(p0.y);
        v0.z = lrelu(p1.x); v0.w = lrelu(p1.y);
        v1.x = lrelu(p2.x); v1.y = lrelu(p2.y);
        v1.z = lrelu(p3.x); v1.w = lrelu(p3.y);
        *(float4*)&dest[o * RP + m0] = v0;
        *(float4*)&dest[o * RP + m1] = v1;
    }
}

__global__ void __launch_bounds__(128) mlp_kernel(const float* __restrict__ xyz,
    const float* __restrict__ wn1, const float* __restrict__ wb1,
    const float* __restrict__ wn2, const float* __restrict__ wb2,
    const float* __restrict__ wn3, const float* __restrict__ wb3)
{
    extern __shared__ float sm[];
    float* bufF = sm;                          // [132][RP]  feats -> h2
    float* bufH = bufF + SMEM_BUF_F;           // [128][RP]  h1 -> h3-half
    float* swB  = bufH + SMEM_BUF_H;           // [16][128]
    float* swm  = swB + SMEM_SWB;              // [64][8]
    int*   sidx = (int*)(swm + SMEM_SWM);      // [64]

    const int pair = blockIdx.x;               // 0..8191
    const int b    = pair >> 10;
    const int t    = threadIdx.x;
    const int tx = t & 15, ty = t >> 4;
    const int o0 = tx * 4, o1 = tx * 4 + 64;
    const int m0 = ty * 4, m1 = ty * 4 + 32;

    const float* X  = xyz + (size_t)b * 3 * Np;
    const float* PT = g_ptsT + (size_t)b * Np * Dp;

    if (t < RR) sidx[t] = g_knn[(size_t)(pair * 2 + (t >> 5)) * Kp + (t & 31)];
    __syncthreads();

    #pragma unroll 4
    for (int m = 0; m < RR; m++) {
        int n = sidx[m];
        bufF[(3 + t) * RP + m] = PT[(size_t)n * Dp + t];
    }
    for (int idx = t; idx < RR * 3; idx += 128) {
        int m = idx / 3, c = idx - m * 3;
        int n = sidx[m];
        int sq = ((pair * 2 + (m >> 5)) & (Sp - 1));
        bufF[c * RP + m] = X[c * Np + n] - X[c * Np + sq];
    }
    if (t < RR) bufF[C0 * RP + t] = 0.0f;
    __syncthreads();

    if (t < RR) {
        float dx = bufF[0 * RP + t], dy = bufF[1 * RP + t], dz = bufF[2 * RP + t];
        float h[8], g[8];
        #pragma unroll
        for (int o = 0; o < 8; o++) {
            float a = wn1[o * 3 + 0] * dx + wn1[o * 3 + 1] * dy + wn1[o * 3 + 2] * dz + wb1[o];
            h[o] = a > 0.0f ? a : 0.0f;
        }
        #pragma unroll
        for (int o = 0; o < 8; o++) {
            float a = wb2[o];
            #pragma unroll
            for (int c = 0; c < 8; c++) a += wn2[o * 8 + c] * h[c];
            g[o] = a > 0.0f ? a : 0.0f;
        }
        #pragma unroll
        for (int o = 0; o < 8; o++) {
            float a = wb3[o];
            #pragma unroll
            for (int c = 0; c < 8; c++) a += wn3[o * 8 + c] * g[c];
            swm[t * 8 + o] = a > 0.0f ? a : 0.0f;
        }
    }

    gemm_layer<C1P, 12>(bufF, g_w1T, 128, 0, swB, bufH, t, o0, o1, m0, m1);
    __syncthreads();
    gemm_layer<M0, 16>(bufH, g_w2T, 128, 0, swB, bufF, t, o0, o1, m0, m1);
    __syncthreads();

    #pragma unroll 1
    for (int p = 0; p < 2; p++) {
        gemm_layer<M1, 16>(bufF, g_w3T, 256, 128 * p, swB, bufH, t, o0, o1, m0, m1);
        __syncthreads();
        {
            int q  = t >> 6;
            int ob = t & 63;
            int gq = pair * 2 + q;
            float* fo = g_flat + (size_t)gq * FLATN + (size_t)(128 * p) * 8;
            const float* wmq = swm + q * Kp * 8;
            #pragma unroll
            for (int oo = 0; oo < 2; oo++) {
                int o = ob + 64 * oo;
                const float* hrow = bufH + o * RP + q * Kp;
                u64t ag2[4];
                #pragma unroll
                for (int w = 0; w < 4; w++) ag2[w] = 0ull;
                #pragma unroll 4
                for (int k = 0; k < Kp; k++) {
                    float h = hrow[k];
                    u64t hd = dup2(h);
                    ulonglong2 wv0 = *(const ulonglong2*)&wmq[k * 8];      // 32B aligned
                    ulonglong2 wv1 = *(const ulonglong2*)&wmq[k * 8 + 4];
                    ffma2(ag2[0], hd, wv0.x);
                    ffma2(ag2[1], hd, wv0.y);
                    ffma2(ag2[2], hd, wv1.x);
                    ffma2(ag2[3], hd, wv1.y);
                }
                float2 g0 = unpack2(ag2[0]), g1 = unpack2(ag2[1]);
                float2 g2 = unpack2(ag2[2]), g3 = unpack2(ag2[3]);
                *(float4*)&fo[o * 8]     = make_float4(g0.x, g0.y, g1.x, g1.y);
                *(float4*)&fo[o * 8 + 4] = make_float4(g2.x, g2.y, g3.x, g3.y);
            }
        }
        __syncthreads();
    }
}

// ---------------------------------------------------------------------------
// Kernel 4: out = lrelu(flat[16384,2048] @ wlin[256,2048]^T) -> out[b][o][s]
// 128x64x16 tile, 256 threads, 8m x 4n per thread, f32x2 + register prefetch.
// ---------------------------------------------------------------------------
#define BM 128
#define BN 64
#define BKk 16
#define BMP (BM + 4)
#define BNP (BN + 4)

__global__ void __launch_bounds__(256) out_gemm_kernel(
    const float* __restrict__ Wl, float* __restrict__ outp)
{
    __shared__ float As[BKk][BMP];
    __shared__ float Bs[BKk][BNP];

    const int bm = blockIdx.x;       // 0..127
    const int bn = blockIdx.y;       // 0..3
    const int t  = threadIdx.x;
    const int mm0 = bm * BM, nn0 = bn * BN;
    const int tx = t & 15, ty = t >> 4;           // 16 x 16
    const int lr = t >> 2;                        // 0..63
    const int lc = (t & 3) * 4;                   // 0,4,8,12

    const float* A = g_flat;

    u64t accp[8][2];    // [m][n-pair]
    #pragma unroll
    for (int i = 0; i < 8; i++) { accp[i][0] = 0ull; accp[i][1] = 0ull; }

    // prefetch chunk 0
    float4 a0 = *(const float4*)(A  + (size_t)(mm0 + lr) * FLATN + lc);
    float4 a1 = *(const float4*)(A  + (size_t)(mm0 + lr + 64) * FLATN + lc);
    float4 bq = *(const float4*)(Wl + (size_t)(nn0 + lr) * FLATN + lc);

    #pragma unroll 1
    for (int k0 = 0; k0 < FLATN; k0 += BKk) {
        __syncthreads();                       // prev compute done with As/Bs
        As[lc + 0][lr] = a0.x; As[lc + 1][lr] = a0.y;
        As[lc + 2][lr] = a0.z; As[lc + 3][lr] = a0.w;
        As[lc + 0][lr + 64] = a1.x; As[lc + 1][lr + 64] = a1.y;
        As[lc + 2][lr + 64] = a1.z; As[lc + 3][lr + 64] = a1.w;
        Bs[lc + 0][lr] = bq.x; Bs[lc + 1][lr] = bq.y;
        Bs[lc + 2][lr] = bq.z; Bs[lc + 3][lr] = bq.w;
        if (k0 + BKk < FLATN) {                // prefetch next chunk
            a0 = *(const float4*)(A  + (size_t)(mm0 + lr) * FLATN + k0 + BKk + lc);
            a1 = *(const float4*)(A  + (size_t)(mm0 + lr + 64) * FLATN + k0 + BKk + lc);
            bq = *(const float4*)(Wl + (size_t)(nn0 + lr) * FLATN + k0 + BKk + lc);
        }
        __syncthreads();
        #pragma unroll
        for (int k = 0; k < BKk; k++) {
            float4 av0 = *(const float4*)&As[k][ty * 4];
            float4 av1 = *(const float4*)&As[k][ty * 4 + 64];
            ulonglong2 bv = *(const ulonglong2*)&Bs[k][tx * 4];   // n-pairs, 16B aligned
            float aa[8] = {av0.x, av0.y, av0.z, av0.w, av1.x, av1.y, av1.z, av1.w};
            #pragma unroll
            for (int i = 0; i < 8; i++) {
                u64t ad = dup2(aa[i]);
                ffma2(accp[i][0], ad, bv.x);
                ffma2(accp[i][1], ad, bv.y);
            }
        }
    }

    #pragma unroll
    for (int i = 0; i < 8; i++) {
        int mm = mm0 + ty * 4 + (i & 3) + ((i >> 2) * 64);
        int bb = mm >> 11, ss = mm & (Sp - 1);
        float* ob = outp + (size_t)bb * M2 * Sp + ss;
        float2 p0 = unpack2(accp[i][0]);
        float2 p1 = unpack2(accp[i][1]);
        float r[4] = {p0.x, p0.y, p1.x, p1.y};
        #pragma unroll
        for (int j = 0; j < 4; j++) {
            ob[(size_t)(nn0 + tx * 4 + j) * Sp] = lrelu(r[j]);
        }
    }
}

// ---------------------------------------------------------------------------
// Launcher
// ---------------------------------------------------------------------------
extern "C" void kernel_launch(void* const* d_in, const int* in_sizes, int n_in,
                              void* d_out, int out_size)
{
    const float* xyz  = (const float*)d_in[0];
    const float* pts  = (const float*)d_in[1];
    const float* w1   = (const float*)d_in[2];
    const float* w2   = (const float*)d_in[3];
    const float* w3   = (const float*)d_in[4];
    const float* wn1  = (const float*)d_in[5];
    const float* wb1  = (const float*)d_in[6];
    const float* wn2  = (const float*)d_in[7];
    const float* wb2  = (const float*)d_in[8];
    const float* wn3  = (const float*)d_in[9];
    const float* wb3  = (const float*)d_in[10];
    const float* wlin = (const float*)d_in[11];
    float* out = (float*)d_out;

    prep_w1T_kernel<<<(C1P * M0 + 255) / 256, 256>>>(w1);
    prep_w2T_kernel<<<(M0 * M1 + 255) / 256, 256>>>(w2);
    prep_w3T_kernel<<<(M1 * M2 + 255) / 256, 256>>>(w3);

    copy_newxyz_kernel<<<(Bb * 3 * Sp + 255) / 256, 256>>>(xyz, out);

    {
        dim3 g(Np / 32, Dp / 32, Bb);
        dim3 blk(32, 8);
        transpose_kernel<<<g, blk>>>(pts);
    }

    knn_kernel<<<Bb * Sp, 256>>>(xyz);

    cudaFuncSetAttribute(mlp_kernel, cudaFuncAttributeMaxDynamicSharedMemorySize, SMEM_BYTES);
    mlp_kernel<<<Bb * Sp / QB, 128, SMEM_BYTES>>>(xyz,
                                                  wn1, wb1, wn2, wb2, wn3, wb3);

    {
        dim3 g((Bb * Sp) / BM, M2 / BN);
        out_gemm_kernel<<<g, 256>>>(wlin, out + Bb * 3 * Sp);
    }
}

// round 11
// speedup vs baseline: 1.3822x; 1.0034x over previous
#include <cuda_runtime.h>
#include <cstdint>

// Problem constants
#define Bb   8
#define Np   8192
#define Sp   2048
#define Kp   32
#define Dp   128
#define C0   131          // D + 3
#define C1P  132          // padded layer-1 input channels
#define M0   128
#define M1   128
#define M2   256
#define HIDp 8
#define LEAKYF 0.1f
#define FLATN (M2*HIDp)   // 2048

// MLP tiling
#define QB   2            // queries per CTA
#define RR   (QB*Kp)      // 64 rows (m)
#define RP   68           // padded m-stride (floats)

// Scratch (device globals: allocation-free rule)
__device__ float g_flat[(size_t)Bb * Sp * FLATN];   // 134 MB
__device__ float g_ptsT[(size_t)Bb * Np * Dp];      // 32 MB  [b][n][c]
__device__ int   g_knn[Bb * Sp * Kp];               // 2 MB
__device__ float g_w1T[C1P * M0];                   // c-major w1 [132][128]
__device__ float g_w2T[M0 * M1];                    // c-major w2 [128][128]
__device__ float g_w3T[M1 * M2];                    // c-major w3 [128][256]

__device__ __forceinline__ float lrelu(float x) { return x > 0.0f ? x : LEAKYF * x; }

// ---- packed fp32x2 helpers (Blackwell sm_100+; bit-exact vs 2x fmaf) ----
typedef unsigned long long u64t;
__device__ __forceinline__ void ffma2(u64t& d, u64t a, u64t b) {
    asm("fma.rn.f32x2 %0, %1, %2, %0;" : "+l"(d) : "l"(a), "l"(b));
}
__device__ __forceinline__ u64t dup2(float x) {
    u64t r; asm("mov.b64 %0, {%1, %2};" : "=l"(r) : "f"(x), "f"(x)); return r;
}
__device__ __forceinline__ float2 unpack2(u64t v) {
    float2 r; asm("mov.b64 {%0, %1}, %2;" : "=f"(r.x), "=f"(r.y) : "l"(v)); return r;
}

// ---------------------------------------------------------------------------
// Prep kernels: transpose weights to c-major
// ---------------------------------------------------------------------------
__global__ void prep_w1T_kernel(const float* __restrict__ w1)
{
    int idx = blockIdx.x * blockDim.x + threadIdx.x;   // c*128 + o
    if (idx >= C1P * M0) return;
    int c = idx >> 7, o = idx & 127;
    g_w1T[idx] = (c < C0) ? w1[o * C0 + c] : 0.0f;
}
__global__ void prep_w2T_kernel(const float* __restrict__ w2)
{
    int idx = blockIdx.x * blockDim.x + threadIdx.x;
    if (idx >= M0 * M1) return;
    int c = idx >> 7, o = idx & 127;
    g_w2T[idx] = w2[o * M0 + c];
}
__global__ void prep_w3T_kernel(const float* __restrict__ w3)
{
    int idx = blockIdx.x * blockDim.x + threadIdx.x;   // c*256 + o
    if (idx >= M1 * M2) return;
    int c = idx >> 8, o = idx & 255;
    g_w3T[idx] = w3[o * M1 + c];
}

// ---------------------------------------------------------------------------
// Kernel 0: copy new_xyz = xyz[:, :, :S] to output head
// ---------------------------------------------------------------------------
__global__ void copy_newxyz_kernel(const float* __restrict__ xyz, float* __restrict__ out)
{
    int idx = blockIdx.x * blockDim.x + threadIdx.x;
    if (idx >= Bb * 3 * Sp) return;
    int b = idx / (3 * Sp);
    int r = idx - b * 3 * Sp;
    int c = r / Sp;
    int s = r - c * Sp;
    out[idx] = xyz[(b * 3 + c) * Np + s];
}

// ---------------------------------------------------------------------------
// Kernel 1: transpose points [B][D][N] -> ptsT [B][N][D]
// ---------------------------------------------------------------------------
__global__ void transpose_kernel(const float* __restrict__ p)
{
    __shared__ float tile[32][33];
    int b  = blockIdx.z;
    int nb = blockIdx.x * 32;
    int cb = blockIdx.y * 32;
    int tx = threadIdx.x;
    int ty = threadIdx.y;
    const float* src = p + (size_t)b * Dp * Np;
    float* dst = g_ptsT + (size_t)b * Np * Dp;
    #pragma unroll
    for (int j = ty; j < 32; j += 8)
        tile[j][tx] = src[(size_t)(cb + j) * Np + nb + tx];
    __syncthreads();
    #pragma unroll
    for (int j = ty; j < 32; j += 8)
        dst[(size_t)(nb + j) * Dp + cb + tx] = tile[tx][j];
}

// ---------------------------------------------------------------------------
// Kernel 2: KNN, round-7 block version (proven fastest).
// Matches jax top_k(-sqr) with index tie-break.
// ---------------------------------------------------------------------------
__global__ void __launch_bounds__(256) knn_kernel(const float* __restrict__ xyz)
{
    const int bs = blockIdx.x;
    const int b  = bs >> 11;
    const int s  = bs & (Sp - 1);
    const float* X = xyz + (size_t)b * 3 * Np;
    const int t = threadIdx.x;

    const float qx = X[s], qy = X[Np + s], qz = X[2 * Np + s];
    const float qq = qx * qx + qy * qy + qz * qz;

    float d[32];
    #pragma unroll
    for (int i = 0; i < 32; i++) {
        int n = t + (i << 8);
        float px = X[n], py = X[Np + n], pz = X[2 * Np + n];
        float pp  = px * px + py * py + pz * pz;
        float dot = qx * px + qy * py + qz * pz;
        d[i] = (qq + pp) - 2.0f * dot;
    }

    float lbv = d[0]; int lbs = 0;
    #pragma unroll
    for (int i = 1; i < 32; i++) if (d[i] < lbv) { lbv = d[i]; lbs = i; }

    __shared__ float bv[256];
    __shared__ int   bi[256];
    __shared__ int   s_sel[Kp];
    __shared__ int   s_cur;

    for (int r = 0; r < Kp; r++) {
        bv[t] = lbv;
        bi[t] = t + (lbs << 8);
        __syncthreads();
        if (t < 32) {
            float v = bv[t]; int id = bi[t];
            #pragma unroll
            for (int j = 1; j < 8; j++) {
                float v2 = bv[t + 32 * j]; int i2 = bi[t + 32 * j];
                if (v2 < v || (v2 == v && i2 < id)) { v = v2; id = i2; }
            }
            #pragma unroll
            for (int off = 16; off > 0; off >>= 1) {
                float v2 = __shfl_down_sync(0xffffffffu, v, off);
                int   i2 = __shfl_down_sync(0xffffffffu, id, off);
                if (v2 < v || (v2 == v && i2 < id)) { v = v2; id = i2; }
            }
            if (t == 0) { s_sel[r] = id; s_cur = id; }
        }
        __syncthreads();
        int cid = s_cur;
        if ((cid & 255) == t) {
            int slot = cid >> 8;
            #pragma unroll
            for (int i = 0; i < 32; i++) if (i == slot) d[i] = 3.0e38f;
            lbv = d[0]; lbs = 0;
            #pragma unroll
            for (int i = 1; i < 32; i++) if (d[i] < lbv) { lbv = d[i]; lbs = i; }
        }
    }
    if (t < Kp) g_knn[bs * Kp + t] = s_sel[t];
}

// ---------------------------------------------------------------------------
// Kernel 3: MLP stack as SGEMM. One CTA = 2 queries (64 rows), 128 threads.
// Packed fp32x2 FMA; weight staging double-buffered -> 1 barrier per K-chunk.
// Accumulation order over c unchanged (ascending) -> bit-identical results.
// ---------------------------------------------------------------------------
#define SMEM_BUF_F (C1P * RP)         // 8976 floats: feats -> h2
#define SMEM_BUF_H (M0 * RP)          // 8704 floats: h1 -> h3-half
#define SWB_MAX    32                 // max BK
#define SMEM_SWB   (2 * SWB_MAX * 128)// 8192 floats (double buffer)
#define SMEM_SWM   (QB * Kp * HIDp)   // 512 floats
#define SMEM_FLOATS (SMEM_BUF_F + SMEM_BUF_H + SMEM_SWB + SMEM_SWM)
#define SMEM_BYTES  (SMEM_FLOATS * 4 + RR * 4)

template<int C, int BK>
__device__ __forceinline__ void gemm_layer(
    const float* __restrict__ Asrc,   // smem [C][RP]
    const float* __restrict__ Wsrc,   // global c-major [C][wstride]
    int wstride, int woff,
    float* __restrict__ swB,          // smem [2][BK][128]
    float* __restrict__ dest,         // smem [128][RP]
    int t, int o0, int o1, int m0, int m1)
{
    constexpr int NCH = C / BK;            // chunks
    constexpr int NV  = (BK * 128) / 512;  // float4 stages per thread
    u64t accp[8][4];                  // [o][m-pair]
    #pragma unroll
    for (int j = 0; j < 8; j++)
        #pragma unroll
        for (int i = 0; i < 4; i++) accp[j][i] = 0ull;

    // load + stage chunk 0 into buffer 0
    float4 wreg[NV];
    #pragma unroll
    for (int v = 0; v < NV; v++) {
        int idx = 4 * t + 512 * v;
        int r = idx >> 7, o = idx & 127;
        wreg[v] = *(const float4*)&Wsrc[(size_t)r * wstride + woff + o];
    }
    __syncthreads();                       // all prior users of swB done
    #pragma unroll
    for (int v = 0; v < NV; v++)
        *(float4*)&swB[4 * t + 512 * v] = wreg[v];

    #pragma unroll 1
    for (int c = 0; c < NCH; c++) {
        __syncthreads();                   // buffer (c&1) fully staged
        const float* cur = swB + (c & 1) * (BK * 128);
        if (c + 1 < NCH) {                 // fetch next chunk (overlaps compute)
            #pragma unroll
            for (int v = 0; v < NV; v++) {
                int idx = 4 * t + 512 * v;
                int r = idx >> 7, o = idx & 127;
                wreg[v] = *(const float4*)&Wsrc[(size_t)((c + 1) * BK + r) * wstride + woff + o];
            }
        }
        #pragma unroll
        for (int kk = 0; kk < BK; kk++) {
            const float* arow = Asrc + (c * BK + kk) * RP;
            ulonglong2 av0 = *(const ulonglong2*)&arow[m0];
            ulonglong2 av1 = *(const ulonglong2*)&arow[m1];
            u64t am2[4] = {av0.x, av0.y, av1.x, av1.y};
            float4 b0 = *(const float4*)&cur[kk * 128 + o0];
            float4 b1 = *(const float4*)&cur[kk * 128 + o1];
            float bo[8] = {b0.x, b0.y, b0.z, b0.w, b1.x, b1.y, b1.z, b1.w};
            #pragma unroll
            for (int j = 0; j < 8; j++) {
                u64t bd = dup2(bo[j]);
                #pragma unroll
                for (int i = 0; i < 4; i++)
                    ffma2(accp[j][i], bd, am2[i]);
            }
        }
        if (c + 1 < NCH) {                 // stage into the other buffer
            float* nxt = swB + ((c + 1) & 1) * (BK * 128);
            #pragma unroll
            for (int v = 0; v < NV; v++)
                *(float4*)&nxt[4 * t + 512 * v] = wreg[v];
        }
    }
    // epilogue stores: dest never aliases Asrc/swB -> no barrier needed here;
    // the caller's __syncthreads() orders dest before its next readers.
    #pragma unroll
    for (int j = 0; j < 8; j++) {
        int o = (j < 4) ? (o0 + j) : (o1 + j - 4);
        float2 p0 = unpack2(accp[j][0]);
        float2 p1 = unpack2(accp[j][1]);
        float2 p2 = unpack2(accp[j][2]);
        float2 p3 = unpack2(accp[j][3]);
        float4 v0, v1;
        v0.x = lrelu(p0.x); v0.y = lrelu(p0.y);
        v0.z = lrelu(p1.x); v0.w = lrelu(p1.y);
        v1.x = lrelu(p2.x); v1.y = lrelu(p2.y);
        v1.z = lrelu(p3.x); v1.w = lrelu(p3.y);
        *(float4*)&dest[o * RP + m0] = v0;
        *(float4*)&dest[o * RP + m1] = v1;
    }
}

__global__ void __launch_bounds__(128) mlp_kernel(const float* __restrict__ xyz,
    const float* __restrict__ wn1, const float* __restrict__ wb1,
    const float* __restrict__ wn2, const float* __restrict__ wb2,
    const float* __restrict__ wn3, const float* __restrict__ wb3)
{
    extern __shared__ float sm[];
    float* bufF = sm;                          // [132][RP]  feats -> h2
    float* bufH = bufF + SMEM_BUF_F;           // [128][RP]  h1 -> h3-half
    float* swB  = bufH + SMEM_BUF_H;           // [2][32][128]
    float* swm  = swB + SMEM_SWB;              // [64][8]
    int*   sidx = (int*)(swm + SMEM_SWM);      // [64]

    const int pair = blockIdx.x;               // 0..8191
    const int b    = pair >> 10;
    const int t    = threadIdx.x;
    const int tx = t & 15, ty = t >> 4;
    const int o0 = tx * 4, o1 = tx * 4 + 64;
    const int m0 = ty * 4, m1 = ty * 4 + 32;

    const float* X  = xyz + (size_t)b * 3 * Np;
    const float* PT = g_ptsT + (size_t)b * Np * Dp;

    if (t < RR) sidx[t] = g_knn[(size_t)(pair * 2 + (t >> 5)) * Kp + (t & 31)];
    __syncthreads();

    #pragma unroll 4
    for (int m = 0; m < RR; m++) {
        int n = sidx[m];
        bufF[(3 + t) * RP + m] = PT[(size_t)n * Dp + t];
    }
    for (int idx = t; idx < RR * 3; idx += 128) {
        int m = idx / 3, c = idx - m * 3;
        int n = sidx[m];
        int sq = ((pair * 2 + (m >> 5)) & (Sp - 1));
        bufF[c * RP + m] = X[c * Np + n] - X[c * Np + sq];
    }
    if (t < RR) bufF[C0 * RP + t] = 0.0f;
    __syncthreads();

    if (t < RR) {
        float dx = bufF[0 * RP + t], dy = bufF[1 * RP + t], dz = bufF[2 * RP + t];
        float h[8], g[8];
        #pragma unroll
        for (int o = 0; o < 8; o++) {
            float a = wn1[o * 3 + 0] * dx + wn1[o * 3 + 1] * dy + wn1[o * 3 + 2] * dz + wb1[o];
            h[o] = a > 0.0f ? a : 0.0f;
        }
        #pragma unroll
        for (int o = 0; o < 8; o++) {
            float a = wb2[o];
            #pragma unroll
            for (int c = 0; c < 8; c++) a += wn2[o * 8 + c] * h[c];
            g[o] = a > 0.0f ? a : 0.0f;
        }
        #pragma unroll
        for (int o = 0; o < 8; o++) {
            float a = wb3[o];
            #pragma unroll
            for (int c = 0; c < 8; c++) a += wn3[o * 8 + c] * g[c];
            swm[t * 8 + o] = a > 0.0f ? a : 0.0f;
        }
    }

    gemm_layer<C1P, 12>(bufF, g_w1T, 128, 0, swB, bufH, t, o0, o1, m0, m1);
    __syncthreads();
    gemm_layer<M0, 32>(bufH, g_w2T, 128, 0, swB, bufF, t, o0, o1, m0, m1);
    __syncthreads();

    #pragma unroll 1
    for (int p = 0; p < 2; p++) {
        gemm_layer<M1, 32>(bufF, g_w3T, 256, 128 * p, swB, bufH, t, o0, o1, m0, m1);
        __syncthreads();
        {
            int q  = t >> 6;
            int ob = t & 63;
            int gq = pair * 2 + q;
            float* fo = g_flat + (size_t)gq * FLATN + (size_t)(128 * p) * 8;
            const float* wmq = swm + q * Kp * 8;
            #pragma unroll
            for (int oo = 0; oo < 2; oo++) {
                int o = ob + 64 * oo;
                const float* hrow = bufH + o * RP + q * Kp;
                u64t ag2[4];
                #pragma unroll
                for (int w = 0; w < 4; w++) ag2[w] = 0ull;
                #pragma unroll 4
                for (int k = 0; k < Kp; k++) {
                    float h = hrow[k];
                    u64t hd = dup2(h);
                    ulonglong2 wv0 = *(const ulonglong2*)&wmq[k * 8];      // 32B aligned
                    ulonglong2 wv1 = *(const ulonglong2*)&wmq[k * 8 + 4];
                    ffma2(ag2[0], hd, wv0.x);
                    ffma2(ag2[1], hd, wv0.y);
                    ffma2(ag2[2], hd, wv1.x);
                    ffma2(ag2[3], hd, wv1.y);
                }
                float2 g0 = unpack2(ag2[0]), g1 = unpack2(ag2[1]);
                float2 g2 = unpack2(ag2[2]), g3 = unpack2(ag2[3]);
                *(float4*)&fo[o * 8]     = make_float4(g0.x, g0.y, g1.x, g1.y);
                *(float4*)&fo[o * 8 + 4] = make_float4(g2.x, g2.y, g3.x, g3.y);
            }
        }
        __syncthreads();
    }
}

// ---------------------------------------------------------------------------
// Kernel 4: out = lrelu(flat[16384,2048] @ wlin[256,2048]^T) -> out[b][o][s]
// 128x64x16 tile, 256 threads, 8m x 4n per thread, f32x2 + register prefetch.
// ---------------------------------------------------------------------------
#define BM 128
#define BN 64
#define BKk 16
#define BMP (BM + 4)
#define BNP (BN + 4)

__global__ void __launch_bounds__(256) out_gemm_kernel(
    const float* __restrict__ Wl, float* __restrict__ outp)
{
    __shared__ float As[BKk][BMP];
    __shared__ float Bs[BKk][BNP];

    const int bm = blockIdx.x;       // 0..127
    const int bn = blockIdx.y;       // 0..3
    const int t  = threadIdx.x;
    const int mm0 = bm * BM, nn0 = bn * BN;
    const int tx = t & 15, ty = t >> 4;           // 16 x 16
    const int lr = t >> 2;                        // 0..63
    const int lc = (t & 3) * 4;                   // 0,4,8,12

    const float* A = g_flat;

    u64t accp[8][2];    // [m][n-pair]
    #pragma unroll
    for (int i = 0; i < 8; i++) { accp[i][0] = 0ull; accp[i][1] = 0ull; }

    // prefetch chunk 0
    float4 a0 = *(const float4*)(A  + (size_t)(mm0 + lr) * FLATN + lc);
    float4 a1 = *(const float4*)(A  + (size_t)(mm0 + lr + 64) * FLATN + lc);
    float4 bq = *(const float4*)(Wl + (size_t)(nn0 + lr) * FLATN + lc);

    #pragma unroll 1
    for (int k0 = 0; k0 < FLATN; k0 += BKk) {
        __syncthreads();                       // prev compute done with As/Bs
        As[lc + 0][lr] = a0.x; As[lc + 1][lr] = a0.y;
        As[lc + 2][lr] = a0.z; As[lc + 3][lr] = a0.w;
        As[lc + 0][lr + 64] = a1.x; As[lc + 1][lr + 64] = a1.y;
        As[lc + 2][lr + 64] = a1.z; As[lc + 3][lr + 64] = a1.w;
        Bs[lc + 0][lr] = bq.x; Bs[lc + 1][lr] = bq.y;
        Bs[lc + 2][lr] = bq.z; Bs[lc + 3][lr] = bq.w;
        if (k0 + BKk < FLATN) {                // prefetch next chunk
            a0 = *(const float4*)(A  + (size_t)(mm0 + lr) * FLATN + k0 + BKk + lc);
            a1 = *(const float4*)(A  + (size_t)(mm0 + lr + 64) * FLATN + k0 + BKk + lc);
            bq = *(const float4*)(Wl + (size_t)(nn0 + lr) * FLATN + k0 + BKk + lc);
        }
        __syncthreads();
        #pragma unroll
        for (int k = 0; k < BKk; k++) {
            float4 av0 = *(const float4*)&As[k][ty * 4];
            float4 av1 = *(const float4*)&As[k][ty * 4 + 64];
            ulonglong2 bv = *(const ulonglong2*)&Bs[k][tx * 4];   // n-pairs, 16B aligned
            float aa[8] = {av0.x, av0.y, av0.z, av0.w, av1.x, av1.y, av1.z, av1.w};
            #pragma unroll
            for (int i = 0; i < 8; i++) {
                u64t ad = dup2(aa[i]);
                ffma2(accp[i][0], ad, bv.x);
                ffma2(accp[i][1], ad, bv.y);
            }
        }
    }

    #pragma unroll
    for (int i = 0; i < 8; i++) {
        int mm = mm0 + ty * 4 + (i & 3) + ((i >> 2) * 64);
        int bb = mm >> 11, ss = mm & (Sp - 1);
        float* ob = outp + (size_t)bb * M2 * Sp + ss;
        float2 p0 = unpack2(accp[i][0]);
        float2 p1 = unpack2(accp[i][1]);
        float r[4] = {p0.x, p0.y, p1.x, p1.y};
        #pragma unroll
        for (int j = 0; j < 4; j++) {
            ob[(size_t)(nn0 + tx * 4 + j) * Sp] = lrelu(r[j]);
        }
    }
}

// ---------------------------------------------------------------------------
// Launcher
// ---------------------------------------------------------------------------
extern "C" void kernel_launch(void* const* d_in, const int* in_sizes, int n_in,
                              void* d_out, int out_size)
{
    const float* xyz  = (const float*)d_in[0];
    const float* pts  = (const float*)d_in[1];
    const float* w1   = (const float*)d_in[2];
    const float* w2   = (const float*)d_in[3];
    const float* w3   = (const float*)d_in[4];
    const float* wn1  = (const float*)d_in[5];
    const float* wb1  = (const float*)d_in[6];
    const float* wn2  = (const float*)d_in[7];
    const float* wb2  = (const float*)d_in[8];
    const float* wn3  = (const float*)d_in[9];
    const float* wb3  = (const float*)d_in[10];
    const float* wlin = (const float*)d_in[11];
    float* out = (float*)d_out;

    prep_w1T_kernel<<<(C1P * M0 + 255) / 256, 256>>>(w1);
    prep_w2T_kernel<<<(M0 * M1 + 255) / 256, 256>>>(w2);
    prep_w3T_kernel<<<(M1 * M2 + 255) / 256, 256>>>(w3);

    copy_newxyz_kernel<<<(Bb * 3 * Sp + 255) / 256, 256>>>(xyz, out);

    {
        dim3 g(Np / 32, Dp / 32, Bb);
        dim3 blk(32, 8);
        transpose_kernel<<<g, blk>>>(pts);
    }

    knn_kernel<<<Bb * Sp, 256>>>(xyz);

    cudaFuncSetAttribute(mlp_kernel, cudaFuncAttributeMaxDynamicSharedMemorySize, SMEM_BYTES);
    mlp_kernel<<<Bb * Sp / QB, 128, SMEM_BYTES>>>(xyz,
                                                  wn1, wb1, wn2, wb2, wn3, wb3);

    {
        dim3 g((Bb * Sp) / BM, M2 / BN);
        out_gemm_kernel<<<g, 256>>>(wlin, out + Bb * 3 * Sp);
    }
}